// round 1
// baseline (speedup 1.0000x reference)
#include <cuda_runtime.h>

#define N_NODES 100000
#define N_EDGES 1600000
#define CC 64
#define NL 3

// Scratch buffers (static device allocation — allowed).
__device__ float g_h [N_NODES * CC];
__device__ float g_xa[N_NODES * CC];
__device__ float g_xb[N_NODES * CC];

static const float BNS = 0.999995000037f; // 1/sqrt(1 + 1e-5)

// h = (1 + eps[layer]) * x   (vectorized)
__global__ void init_h_kernel(const float* __restrict__ x,
                              const float* __restrict__ eps, int layer,
                              float* __restrict__ h) {
    int i = blockIdx.x * blockDim.x + threadIdx.x;
    if (i >= N_NODES * CC / 4) return;
    float e = 1.0f + eps[layer];
    float4 v = ((const float4*)x)[i];
    v.x *= e; v.y *= e; v.z *= e; v.w *= e;
    ((float4*)h)[i] = v;
}

// h[dst] += x[src], 16 threads (one float4 each) per edge.
__global__ void scatter_kernel(const float* __restrict__ x,
                               const int* __restrict__ ei,
                               float* __restrict__ h) {
    long long gid = (long long)blockIdx.x * blockDim.x + threadIdx.x;
    if (gid >= (long long)N_EDGES * 16) return;
    int e  = (int)(gid >> 4);
    int c4 = (int)(gid & 15);
    int src = __ldg(ei + e);
    int dst = __ldg(ei + N_EDGES + e);
    float4 v = *(const float4*)(x + (size_t)src * CC + c4 * 4);
    atomicAdd((float4*)(h + (size_t)dst * CC + c4 * 4), v);
}

// Fused MLP: out = [relu?] bn_out( relu(bn2(relu(bn1(h@W1+b1)) @ W2 + b2)) )
// BN folded into weight columns + bias. 128-row tiles, 256 threads,
// thread (tx,ty) computes an 8-row x 4-col micro-tile.
__global__ void __launch_bounds__(256)
mlp_kernel(const float* __restrict__ h, float* __restrict__ out,
           const float* __restrict__ W1, const float* __restrict__ b1,
           const float* __restrict__ g1, const float* __restrict__ be1,
           const float* __restrict__ W2, const float* __restrict__ b2,
           const float* __restrict__ g2, const float* __restrict__ be2,
           const float* __restrict__ bng, const float* __restrict__ bnb,
           int do_relu) {
    extern __shared__ float smem[];
    float* sW1 = smem;                 // [64][64]  (k-major rows, j contiguous)
    float* sW2 = smem + 64 * 64;       // [64][64]
    float* sH  = smem + 2 * 64 * 64;   // [128][65] pitch 65 (conflict-free)
    const float bns = 0.999995000037f;

    int tid = threadIdx.x;

    // Load BN-folded weights.
    for (int idx = tid; idx < 64 * 64; idx += 256) {
        int j = idx & 63;
        sW1[idx] = W1[idx] * (g1[j] * bns);
        sW2[idx] = W2[idx] * (g2[j] * bns);
    }

    // Load H tile (float4-coalesced).
    int rowbase = blockIdx.x * 128;
    for (int idx = tid; idx < 128 * 16; idx += 256) {
        int r  = idx >> 4;
        int c4 = idx & 15;
        int gr = rowbase + r;
        float4 v = (gr < N_NODES) ? *(const float4*)(h + (size_t)gr * CC + c4 * 4)
                                  : make_float4(0.f, 0.f, 0.f, 0.f);
        float* p = &sH[r * 65 + c4 * 4];
        p[0] = v.x; p[1] = v.y; p[2] = v.z; p[3] = v.w;
    }
    __syncthreads();

    int tx = tid & 15;   // column group (4 cols)
    int ty = tid >> 4;   // row group (8 rows)
    int jb = tx * 4;

    float acc[8][4];

    // ---- GEMM 1: z1 = h @ W1f + c1 ----
    #pragma unroll
    for (int c = 0; c < 4; c++) {
        float cb = b1[jb + c] * (g1[jb + c] * bns) + be1[jb + c];
        #pragma unroll
        for (int r = 0; r < 8; r++) acc[r][c] = cb;
    }
    #pragma unroll 4
    for (int k = 0; k < 64; k++) {
        float4 b = *(float4*)&sW1[k * 64 + jb];
        #pragma unroll
        for (int r = 0; r < 8; r++) {
            float a = sH[(ty * 8 + r) * 65 + k];
            acc[r][0] += a * b.x; acc[r][1] += a * b.y;
            acc[r][2] += a * b.z; acc[r][3] += a * b.w;
        }
    }
    __syncthreads();  // everyone done reading sH before overwrite

    // ReLU, write h1 back to sH.
    #pragma unroll
    for (int r = 0; r < 8; r++) {
        #pragma unroll
        for (int c = 0; c < 4; c++)
            sH[(ty * 8 + r) * 65 + jb + c] = fmaxf(acc[r][c], 0.0f);
    }
    __syncthreads();

    // ---- GEMM 2: z2 = h1 @ W2f + c2 ----
    #pragma unroll
    for (int c = 0; c < 4; c++) {
        float cb = b2[jb + c] * (g2[jb + c] * bns) + be2[jb + c];
        #pragma unroll
        for (int r = 0; r < 8; r++) acc[r][c] = cb;
    }
    #pragma unroll 4
    for (int k = 0; k < 64; k++) {
        float4 b = *(float4*)&sW2[k * 64 + jb];
        #pragma unroll
        for (int r = 0; r < 8; r++) {
            float a = sH[(ty * 8 + r) * 65 + k];
            acc[r][0] += a * b.x; acc[r][1] += a * b.y;
            acc[r][2] += a * b.z; acc[r][3] += a * b.w;
        }
    }

    // ReLU + outer BN (+ optional ReLU), write out.
    #pragma unroll
    for (int r = 0; r < 8; r++) {
        int gr = rowbase + ty * 8 + r;
        if (gr >= N_NODES) continue;
        float4 o;
        float v0 = fmaxf(acc[r][0], 0.0f);
        float v1 = fmaxf(acc[r][1], 0.0f);
        float v2 = fmaxf(acc[r][2], 0.0f);
        float v3 = fmaxf(acc[r][3], 0.0f);
        o.x = bng[jb + 0] * bns * v0 + bnb[jb + 0];
        o.y = bng[jb + 1] * bns * v1 + bnb[jb + 1];
        o.z = bng[jb + 2] * bns * v2 + bnb[jb + 2];
        o.w = bng[jb + 3] * bns * v3 + bnb[jb + 3];
        if (do_relu) {
            o.x = fmaxf(o.x, 0.f); o.y = fmaxf(o.y, 0.f);
            o.z = fmaxf(o.z, 0.f); o.w = fmaxf(o.w, 0.f);
        }
        *(float4*)(out + (size_t)gr * CC + jb) = o;
    }
}

extern "C" void kernel_launch(void* const* d_in, const int* in_sizes, int n_in,
                              void* d_out, int out_size) {
    const float* x   = (const float*)d_in[0];
    const int*   ei  = (const int*)d_in[1];
    const float* eps = (const float*)d_in[2];
    const float* W1  = (const float*)d_in[3];
    const float* b1  = (const float*)d_in[4];
    const float* g1  = (const float*)d_in[5];
    const float* be1 = (const float*)d_in[6];
    const float* W2  = (const float*)d_in[7];
    const float* b2  = (const float*)d_in[8];
    const float* g2  = (const float*)d_in[9];
    const float* be2 = (const float*)d_in[10];
    const float* bng = (const float*)d_in[11];
    const float* bnb = (const float*)d_in[12];
    float* out = (float*)d_out;

    float *hb, *xa, *xb;
    cudaGetSymbolAddress((void**)&hb, g_h);
    cudaGetSymbolAddress((void**)&xa, g_xa);
    cudaGetSymbolAddress((void**)&xb, g_xb);

    const int smem_bytes = (2 * 64 * 64 + 128 * 65) * 4;  // 66048
    cudaFuncSetAttribute(mlp_kernel,
                         cudaFuncAttributeMaxDynamicSharedMemorySize, smem_bytes);

    const int mlp_blocks = (N_NODES + 127) / 128;              // 782
    const int sc_blocks  = (int)(((long long)N_EDGES * 16 + 255) / 256); // 100000
    const int in_blocks  = (N_NODES * CC / 4 + 255) / 256;     // 6250

    const float* xin = x;
    float* outs[NL] = {xa, xb, out};

    for (int l = 0; l < NL; l++) {
        init_h_kernel<<<in_blocks, 256>>>(xin, eps, l, hb);
        scatter_kernel<<<sc_blocks, 256>>>(xin, ei, hb);
        mlp_kernel<<<mlp_blocks, 256, smem_bytes>>>(
            hb, outs[l],
            W1 + l * 64 * 64, b1 + l * 64, g1 + l * 64, be1 + l * 64,
            W2 + l * 64 * 64, b2 + l * 64, g2 + l * 64, be2 + l * 64,
            bng + l * 64, bnb + l * 64, (l < NL - 1) ? 1 : 0);
        xin = outs[l];
    }
}

// round 2
// speedup vs baseline: 1.3172x; 1.3172x over previous
#include <cuda_runtime.h>

#define N_NODES 100000
#define N_EDGES 1600000
#define CC 64
#define NL 3
#define SCAN_BLK 1024
#define N_SCANB ((N_NODES + SCAN_BLK - 1) / SCAN_BLK)   // 98

// Static device scratch (allowed).
__device__ float g_h [N_NODES * CC];
__device__ float g_xa[N_NODES * CC];
__device__ float g_xb[N_NODES * CC];
__device__ int   g_cnt[N_NODES];
__device__ int   g_off[N_NODES];
__device__ int   g_cur[N_NODES];
__device__ int   g_csr[N_EDGES];
__device__ int   g_bsum[N_SCANB + 1];

// ---------------- CSR build (once per launch, reused for 3 layers) ----------

__global__ void hist_kernel(const int* __restrict__ ei, int* __restrict__ cnt) {
    int e = blockIdx.x * blockDim.x + threadIdx.x;
    if (e < N_EDGES) atomicAdd(&cnt[ei[N_EDGES + e]], 1);
}

__global__ void scan_blocks_kernel(const int* __restrict__ cnt,
                                   int* __restrict__ off, int* __restrict__ bsum) {
    __shared__ int sm[SCAN_BLK];
    int gid = blockIdx.x * SCAN_BLK + threadIdx.x;
    int v = (gid < N_NODES) ? cnt[gid] : 0;
    sm[threadIdx.x] = v;
    __syncthreads();
    #pragma unroll
    for (int o = 1; o < SCAN_BLK; o <<= 1) {
        int t = (threadIdx.x >= o) ? sm[threadIdx.x - o] : 0;
        __syncthreads();
        sm[threadIdx.x] += t;
        __syncthreads();
    }
    if (gid < N_NODES) off[gid] = sm[threadIdx.x] - v;  // exclusive
    if (threadIdx.x == SCAN_BLK - 1) bsum[blockIdx.x] = sm[threadIdx.x];
}

__global__ void scan_bsum_kernel(int* __restrict__ bsum) {
    if (threadIdx.x == 0) {
        int acc = 0;
        for (int i = 0; i < N_SCANB; i++) { int t = bsum[i]; bsum[i] = acc; acc += t; }
    }
}

__global__ void add_off_kernel(int* __restrict__ off, const int* __restrict__ bsum,
                               int* __restrict__ cur) {
    int gid = blockIdx.x * blockDim.x + threadIdx.x;
    if (gid < N_NODES) {
        int v = off[gid] + bsum[gid / SCAN_BLK];
        off[gid] = v;
        cur[gid] = v;
    }
}

__global__ void fill_csr_kernel(const int* __restrict__ ei,
                                int* __restrict__ cur, int* __restrict__ csr) {
    int e = blockIdx.x * blockDim.x + threadIdx.x;
    if (e < N_EDGES) {
        int d = ei[N_EDGES + e];
        int p = atomicAdd(&cur[d], 1);
        csr[p] = ei[e];
    }
}

// ---------------- Aggregation: warp-per-node, no atomics --------------------
// h[n] = (1+eps)*x[n] + sum_{s in csr segment of n} x[s]

__global__ void __launch_bounds__(256)
agg_kernel(const float* __restrict__ x, const int* __restrict__ off,
           const int* __restrict__ cnt, const int* __restrict__ csr,
           const float* __restrict__ eps, int layer, float* __restrict__ h) {
    int warp = (blockIdx.x * blockDim.x + threadIdx.x) >> 5;
    int lane = threadIdx.x & 31;
    if (warp >= N_NODES) return;
    int base = off[warp];
    int deg  = cnt[warp];

    float2 acc = make_float2(0.f, 0.f);
    for (int c = 0; c < deg; c += 32) {
        int rem = deg - c;
        int m = rem < 32 ? rem : 32;
        int myi = (lane < m) ? __ldg(&csr[base + c + lane]) : 0;
        for (int j = 0; j < m; j++) {
            int s = __shfl_sync(0xffffffffu, myi, j);
            float2 v = *(const float2*)(x + (size_t)s * CC + lane * 2);
            acc.x += v.x; acc.y += v.y;
        }
    }
    float e = 1.0f + __ldg(&eps[layer]);
    float2 xv = *(const float2*)(x + (size_t)warp * CC + lane * 2);
    acc.x = fmaf(e, xv.x, acc.x);
    acc.y = fmaf(e, xv.y, acc.y);
    *(float2*)(h + (size_t)warp * CC + lane * 2) = acc;
}

// ---------------- Fused MLP (BN folded), unchanged from R1 ------------------

__global__ void __launch_bounds__(256)
mlp_kernel(const float* __restrict__ h, float* __restrict__ out,
           const float* __restrict__ W1, const float* __restrict__ b1,
           const float* __restrict__ g1, const float* __restrict__ be1,
           const float* __restrict__ W2, const float* __restrict__ b2,
           const float* __restrict__ g2, const float* __restrict__ be2,
           const float* __restrict__ bng, const float* __restrict__ bnb,
           int do_relu) {
    extern __shared__ float smem[];
    float* sW1 = smem;
    float* sW2 = smem + 64 * 64;
    float* sH  = smem + 2 * 64 * 64;   // [128][65]
    const float bns = 0.999995000037f; // 1/sqrt(1+1e-5)

    int tid = threadIdx.x;
    for (int idx = tid; idx < 64 * 64; idx += 256) {
        int j = idx & 63;
        sW1[idx] = W1[idx] * (g1[j] * bns);
        sW2[idx] = W2[idx] * (g2[j] * bns);
    }
    int rowbase = blockIdx.x * 128;
    for (int idx = tid; idx < 128 * 16; idx += 256) {
        int r = idx >> 4, c4 = idx & 15;
        int gr = rowbase + r;
        float4 v = (gr < N_NODES) ? *(const float4*)(h + (size_t)gr * CC + c4 * 4)
                                  : make_float4(0.f, 0.f, 0.f, 0.f);
        float* p = &sH[r * 65 + c4 * 4];
        p[0] = v.x; p[1] = v.y; p[2] = v.z; p[3] = v.w;
    }
    __syncthreads();

    int tx = tid & 15, ty = tid >> 4;
    int jb = tx * 4;
    float acc[8][4];

    #pragma unroll
    for (int c = 0; c < 4; c++) {
        float cb = b1[jb + c] * (g1[jb + c] * bns) + be1[jb + c];
        #pragma unroll
        for (int r = 0; r < 8; r++) acc[r][c] = cb;
    }
    #pragma unroll 4
    for (int k = 0; k < 64; k++) {
        float4 b = *(float4*)&sW1[k * 64 + jb];
        #pragma unroll
        for (int r = 0; r < 8; r++) {
            float a = sH[(ty * 8 + r) * 65 + k];
            acc[r][0] += a * b.x; acc[r][1] += a * b.y;
            acc[r][2] += a * b.z; acc[r][3] += a * b.w;
        }
    }
    __syncthreads();
    #pragma unroll
    for (int r = 0; r < 8; r++)
        #pragma unroll
        for (int c = 0; c < 4; c++)
            sH[(ty * 8 + r) * 65 + jb + c] = fmaxf(acc[r][c], 0.0f);
    __syncthreads();

    #pragma unroll
    for (int c = 0; c < 4; c++) {
        float cb = b2[jb + c] * (g2[jb + c] * bns) + be2[jb + c];
        #pragma unroll
        for (int r = 0; r < 8; r++) acc[r][c] = cb;
    }
    #pragma unroll 4
    for (int k = 0; k < 64; k++) {
        float4 b = *(float4*)&sW2[k * 64 + jb];
        #pragma unroll
        for (int r = 0; r < 8; r++) {
            float a = sH[(ty * 8 + r) * 65 + k];
            acc[r][0] += a * b.x; acc[r][1] += a * b.y;
            acc[r][2] += a * b.z; acc[r][3] += a * b.w;
        }
    }

    #pragma unroll
    for (int r = 0; r < 8; r++) {
        int gr = rowbase + ty * 8 + r;
        if (gr >= N_NODES) continue;
        float4 o;
        float v0 = fmaxf(acc[r][0], 0.0f);
        float v1 = fmaxf(acc[r][1], 0.0f);
        float v2 = fmaxf(acc[r][2], 0.0f);
        float v3 = fmaxf(acc[r][3], 0.0f);
        o.x = bng[jb + 0] * bns * v0 + bnb[jb + 0];
        o.y = bng[jb + 1] * bns * v1 + bnb[jb + 1];
        o.z = bng[jb + 2] * bns * v2 + bnb[jb + 2];
        o.w = bng[jb + 3] * bns * v3 + bnb[jb + 3];
        if (do_relu) {
            o.x = fmaxf(o.x, 0.f); o.y = fmaxf(o.y, 0.f);
            o.z = fmaxf(o.z, 0.f); o.w = fmaxf(o.w, 0.f);
        }
        *(float4*)(out + (size_t)gr * CC + jb) = o;
    }
}

extern "C" void kernel_launch(void* const* d_in, const int* in_sizes, int n_in,
                              void* d_out, int out_size) {
    const float* x   = (const float*)d_in[0];
    const int*   ei  = (const int*)d_in[1];
    const float* eps = (const float*)d_in[2];
    const float* W1  = (const float*)d_in[3];
    const float* b1  = (const float*)d_in[4];
    const float* g1  = (const float*)d_in[5];
    const float* be1 = (const float*)d_in[6];
    const float* W2  = (const float*)d_in[7];
    const float* b2  = (const float*)d_in[8];
    const float* g2  = (const float*)d_in[9];
    const float* be2 = (const float*)d_in[10];
    const float* bng = (const float*)d_in[11];
    const float* bnb = (const float*)d_in[12];
    float* out = (float*)d_out;

    float *hb, *xa, *xb;
    int *cnt, *off, *cur, *csr, *bsum;
    cudaGetSymbolAddress((void**)&hb,   g_h);
    cudaGetSymbolAddress((void**)&xa,   g_xa);
    cudaGetSymbolAddress((void**)&xb,   g_xb);
    cudaGetSymbolAddress((void**)&cnt,  g_cnt);
    cudaGetSymbolAddress((void**)&off,  g_off);
    cudaGetSymbolAddress((void**)&cur,  g_cur);
    cudaGetSymbolAddress((void**)&csr,  g_csr);
    cudaGetSymbolAddress((void**)&bsum, g_bsum);

    const int smem_bytes = (2 * 64 * 64 + 128 * 65) * 4;  // 66048
    cudaFuncSetAttribute(mlp_kernel,
                         cudaFuncAttributeMaxDynamicSharedMemorySize, smem_bytes);

    const int eblk = (N_EDGES + 255) / 256;       // 6250
    const int nblk = (N_NODES + 255) / 256;       // 391
    const int mlp_blocks = (N_NODES + 127) / 128; // 782
    const int agg_blocks = (N_NODES * 32 + 255) / 256; // 12500

    // CSR build (edge_index constant across layers).
    cudaMemsetAsync(cnt, 0, N_NODES * sizeof(int));
    hist_kernel<<<eblk, 256>>>(ei, cnt);
    scan_blocks_kernel<<<N_SCANB, SCAN_BLK>>>(cnt, off, bsum);
    scan_bsum_kernel<<<1, 32>>>(bsum);
    add_off_kernel<<<nblk, 256>>>(off, bsum, cur);
    fill_csr_kernel<<<eblk, 256>>>(ei, cur, csr);

    const float* xin = x;
    float* outs[NL] = {xa, xb, out};
    for (int l = 0; l < NL; l++) {
        agg_kernel<<<agg_blocks, 256>>>(xin, off, cnt, csr, eps, l, hb);
        mlp_kernel<<<mlp_blocks, 256, smem_bytes>>>(
            hb, outs[l],
            W1 + l * 64 * 64, b1 + l * 64, g1 + l * 64, be1 + l * 64,
            W2 + l * 64 * 64, b2 + l * 64, g2 + l * 64, be2 + l * 64,
            bng + l * 64, bnb + l * 64, (l < NL - 1) ? 1 : 0);
        xin = outs[l];
    }
}